// round 2
// baseline (speedup 1.0000x reference)
#include <cuda_runtime.h>
#include <cstdint>

#define B_N   8
#define CIN   64
#define CATT  32
#define BD    5
#define H     128
#define W     128
#define HW    (H*W)            /* 16384 */
#define CH_STRIDE (BD*HW)      /* 81920 */
#define TY 16
#define TW 64

// scratch for q, k, v : 8*32*5*128*128 floats each (83.9 MB) — static device arrays
__device__ __align__(128) float g_q[(size_t)B_N*CATT*BD*HW];
__device__ __align__(128) float g_k[(size_t)B_N*CATT*BD*HW];
__device__ __align__(128) float g_v[(size_t)B_N*CATT*BD*HW];

// ---- f32x2 helpers (FFMA2 path; ptxas will not auto-fuse from C++) ----
__device__ __forceinline__ unsigned long long pk(float lo, float hi) {
    unsigned long long r;
    asm("mov.b64 %0, {%1, %2};" : "=l"(r) : "f"(lo), "f"(hi));
    return r;
}
__device__ __forceinline__ void fma2(unsigned long long& d,
                                     unsigned long long a,
                                     unsigned long long b) {
    asm("fma.rn.f32x2 %0, %1, %2, %0;" : "+l"(d) : "l"(a), "l"(b));
}
__device__ __forceinline__ float2 u2f(unsigned long long u) {
    float2 f;
    asm("mov.b64 {%0, %1}, %2;" : "=f"(f.x), "=f"(f.y) : "l"(u));
    return f;
}
__device__ __forceinline__ float lo32(unsigned long long u) {
    float f; asm("{ .reg .f32 t; mov.b64 {%0, t}, %1; }" : "=f"(f) : "l"(u));
    return f;
}
__device__ __forceinline__ float hi32(unsigned long long u) {
    float f; asm("{ .reg .f32 t; mov.b64 {t, %0}, %1; }" : "=f"(f) : "l"(u));
    return f;
}

// ============================================================================
// Grouped 3x3x3 conv, groups=32 (2 in-ch per out-ch). NC=1: q from x.
// NC=2: k and v from last (shared input tile).
// Block: 256 threads, tile TY=16 x TW=64, one (batch, out-channel) per block.z.
// Each thread: 4 consecutive w outputs x 5 B outputs, accumulators packed
// pairwise along w as f32x2.
// ============================================================================
template<int NC>
__global__ __launch_bounds__(256, 2)
void conv3d_kernel(const float* __restrict__ in,
                   const float* __restrict__ wA,
                   const float* __restrict__ wB)
{
    __shared__ float  tile[2][BD][TY+2][TW+2];
    __shared__ float2 wsp[2][54];     // (w,w) broadcast pairs

    const int tid = threadIdx.x;
    const int c   = blockIdx.z & 31;
    const int bb  = blockIdx.z >> 5;
    const int y0  = blockIdx.y * TY;
    const int x0  = blockIdx.x * TW;

    if (tid < 54) {
        float a = wA[c*54 + tid];
        wsp[0][tid] = make_float2(a, a);
        if (NC == 2) {
            float b = wB[c*54 + tid];
            wsp[1][tid] = make_float2(b, b);
        }
    }

    // ---- halo tile load: no div/mod. Threads = 64 cols x 4 rows. ----
    {
        const int lx = tid & 63;       // 0..63
        const int lr = tid >> 6;       // 0..3
        const int gx  = x0 - 1 + lx;
        const int gx2 = gx + 64;
        const bool okx  = (unsigned)gx  < (unsigned)W;
        const bool halo = (lx < 2);
        const bool okx2 = halo && ((unsigned)gx2 < (unsigned)W);
        const float* inb = in + ((size_t)(bb*CIN + 2*c))*CH_STRIDE;

        #pragma unroll
        for (int din = 0; din < 2; ++din) {
            #pragma unroll
            for (int Bi = 0; Bi < BD; ++Bi) {
                const float* src = inb + (din*BD + Bi)*HW;
                #pragma unroll
                for (int t = 0; t < 5; ++t) {
                    const int yy = lr + 4*t;
                    if (yy >= TY+2) break;
                    const int gy = y0 - 1 + yy;
                    const bool oky = (unsigned)gy < (unsigned)H;
                    const int rb = gy*W;
                    float v = (oky & okx) ? src[rb + gx] : 0.f;
                    tile[din][Bi][yy][lx] = v;
                    if (halo) {
                        float v2 = (oky & okx2) ? src[rb + gx2] : 0.f;
                        tile[din][Bi][yy][lx + 64] = v2;
                    }
                }
            }
        }
    }
    __syncthreads();

    const int ty  = tid >> 4;
    const int tx4 = (tid & 15) << 2;

    unsigned long long acc[NC][BD][2];
    #pragma unroll
    for (int n = 0; n < NC; ++n)
        #pragma unroll
        for (int bo = 0; bo < BD; ++bo) { acc[n][bo][0] = 0ull; acc[n][bo][1] = 0ull; }

    #pragma unroll
    for (int din = 0; din < 2; ++din) {
        #pragma unroll
        for (int dy = 0; dy < 3; ++dy) {
            unsigned long long wr2[NC][9];
            #pragma unroll
            for (int n = 0; n < NC; ++n)
                #pragma unroll
                for (int dB = 0; dB < 3; ++dB)
                    #pragma unroll
                    for (int dx = 0; dx < 3; ++dx)
                        wr2[n][dB*3+dx] =
                            *(const unsigned long long*)&wsp[n][din*27 + dB*9 + dy*3 + dx];

            #pragma unroll
            for (int Bi = 0; Bi < BD; ++Bi) {
                const float* rp = &tile[din][Bi][ty + dy][tx4];
                unsigned long long P[5];
                P[0] = *(const unsigned long long*)(rp);        // (x0,x1)
                P[2] = *(const unsigned long long*)(rp + 2);    // (x2,x3)
                P[4] = *(const unsigned long long*)(rp + 4);    // (x4,x5)
                P[1] = pk(hi32(P[0]), lo32(P[2]));              // (x1,x2)
                P[3] = pk(hi32(P[2]), lo32(P[4]));              // (x3,x4)
                #pragma unroll
                for (int dB = 0; dB < 3; ++dB) {
                    const int Bo = Bi + 1 - dB;
                    if (Bo < 0 || Bo >= BD) continue;
                    #pragma unroll
                    for (int dx = 0; dx < 3; ++dx) {
                        #pragma unroll
                        for (int n = 0; n < NC; ++n) {
                            fma2(acc[n][Bo][0], P[dx],     wr2[n][dB*3+dx]);
                            fma2(acc[n][Bo][1], P[dx + 2], wr2[n][dB*3+dx]);
                        }
                    }
                }
            }
        }
    }

    const size_t ob = ((size_t)(bb*CATT + c))*CH_STRIDE
                    + (size_t)(y0 + ty)*W + x0 + tx4;
    #pragma unroll
    for (int Bo = 0; Bo < BD; ++Bo) {
        float2 a0 = u2f(acc[0][Bo][0]);
        float2 a1 = u2f(acc[0][Bo][1]);
        float4 r0 = make_float4(a0.x, a0.y, a1.x, a1.y);
        if (NC == 1) {
            *(float4*)(g_q + ob + (size_t)Bo*HW) = r0;
        } else {
            *(float4*)(g_k + ob + (size_t)Bo*HW) = r0;
            float2 b0 = u2f(acc[1][Bo][0]);
            float2 b1 = u2f(acc[1][Bo][1]);
            *(float4*)(g_v + ob + (size_t)Bo*HW) = make_float4(b0.x, b0.y, b1.x, b1.y);
        }
    }
}

// ============================================================================
// Attention (over B=5, 8 heads, head_dim=4) + grouped 1x1x1 projection.
// One thread per (b, y, x) point; loops heads; coalesced along x.
// ============================================================================
__global__ __launch_bounds__(256)
void attn_proj_kernel(const float* __restrict__ wproj, float* __restrict__ out)
{
    __shared__ float wp[64];
    if (threadIdx.x < 64) wp[threadIdx.x] = wproj[threadIdx.x];
    __syncthreads();

    const int p = blockIdx.x * 256 + threadIdx.x;
    if (p >= B_N * HW) return;
    const int bb = p >> 14;
    const int yx = p & (HW - 1);
    const size_t base = (size_t)bb * CATT * CH_STRIDE + yx;

    const float SCALE = 0.35355339059327373f;   // 8^{-1/2}

    #pragma unroll 1
    for (int hd = 0; hd < 8; ++hd) {
        float q[BD][4], k[BD][4], v[BD][4];
        #pragma unroll
        for (int d = 0; d < 4; ++d) {
            const size_t cb = base + (size_t)(hd*4 + d) * CH_STRIDE;
            #pragma unroll
            for (int Bi = 0; Bi < BD; ++Bi) {
                q[Bi][d] = g_q[cb + Bi*HW] * SCALE;
                k[Bi][d] = g_k[cb + Bi*HW];
                v[Bi][d] = g_v[cb + Bi*HW];
            }
        }
        #pragma unroll
        for (int i = 0; i < BD; ++i) {
            float s[BD];
            #pragma unroll
            for (int j = 0; j < BD; ++j) {
                float t = q[i][0] * k[j][0];
                t = fmaf(q[i][1], k[j][1], t);
                t = fmaf(q[i][2], k[j][2], t);
                t = fmaf(q[i][3], k[j][3], t);
                s[j] = t;
            }
            float m = s[0];
            #pragma unroll
            for (int j = 1; j < BD; ++j) m = fmaxf(m, s[j]);
            float e[BD], sum = 0.f;
            #pragma unroll
            for (int j = 0; j < BD; ++j) { e[j] = __expf(s[j] - m); sum += e[j]; }
            const float inv = 1.0f / sum;
            #pragma unroll
            for (int d = 0; d < 4; ++d) {
                float t = e[0] * v[0][d];
                #pragma unroll
                for (int j = 1; j < BD; ++j) t = fmaf(e[j], v[j][d], t);
                const float od = t * inv;
                const int ch = hd*4 + d;
                const size_t obx = ((size_t)(bb*CIN + 2*ch)*BD + i)*HW + yx;
                out[obx]           = od * wp[2*ch];
                out[obx + (size_t)BD*HW] = od * wp[2*ch + 1];
            }
        }
    }
}

extern "C" void kernel_launch(void* const* d_in, const int* in_sizes, int n_in,
                              void* d_out, int out_size) {
    const float* x     = (const float*)d_in[0];
    const float* last  = (const float*)d_in[1];
    const float* wq    = (const float*)d_in[2];
    const float* wk    = (const float*)d_in[3];
    const float* wv    = (const float*)d_in[4];
    const float* wproj = (const float*)d_in[5];
    float* out = (float*)d_out;

    dim3 cgrid(W/TW, H/TY, B_N*CATT);   // (2, 8, 256)
    conv3d_kernel<1><<<cgrid, 256>>>(x,    wq, nullptr);
    conv3d_kernel<2><<<cgrid, 256>>>(last, wk, wv);
    attn_proj_kernel<<<(B_N*HW + 255)/256, 256>>>(wproj, out);
}

// round 3
// speedup vs baseline: 3.2121x; 3.2121x over previous
#include <cuda_runtime.h>
#include <cstdint>

#define B_N   8
#define CIN   64
#define CATT  32
#define BD    5
#define H     128
#define W     128
#define HW    (H*W)            /* 16384 */
#define CH_STRIDE (BD*HW)      /* 81920 */
#define TY 16
#define TW 64

// scratch for q, k, v : 8*32*5*128*128 floats each (83.9 MB) — static device arrays
__device__ __align__(128) float g_q[(size_t)B_N*CATT*BD*HW];
__device__ __align__(128) float g_k[(size_t)B_N*CATT*BD*HW];
__device__ __align__(128) float g_v[(size_t)B_N*CATT*BD*HW];

// ---- f32x2 helpers (FFMA2 path; ptxas will not auto-fuse from C++) ----
__device__ __forceinline__ unsigned long long pk(float lo, float hi) {
    unsigned long long r;
    asm("mov.b64 %0, {%1, %2};" : "=l"(r) : "f"(lo), "f"(hi));
    return r;
}
__device__ __forceinline__ void fma2(unsigned long long& d,
                                     unsigned long long a,
                                     unsigned long long b) {
    asm("fma.rn.f32x2 %0, %1, %2, %0;" : "+l"(d) : "l"(a), "l"(b));
}
__device__ __forceinline__ float2 u2f(unsigned long long u) {
    float2 f;
    asm("mov.b64 {%0, %1}, %2;" : "=f"(f.x), "=f"(f.y) : "l"(u));
    return f;
}
__device__ __forceinline__ float lo32(unsigned long long u) {
    float f; asm("{ .reg .f32 t; mov.b64 {%0, t}, %1; }" : "=f"(f) : "l"(u));
    return f;
}
__device__ __forceinline__ float hi32(unsigned long long u) {
    float f; asm("{ .reg .f32 t; mov.b64 {t, %0}, %1; }" : "=f"(f) : "l"(u));
    return f;
}

// ============================================================================
// Grouped 3x3x3 conv, groups=32 (2 in-ch per out-ch). NC=1: q from x.
// NC=2: k and v from last (shared input tile).
// Block: 256 threads, tile TY=16 x TW=64, one (batch, out-channel) per block.z.
// Each thread: 4 consecutive w outputs x 5 B outputs, accumulators packed
// pairwise along w as f32x2.
// ============================================================================
template<int NC>
__global__ __launch_bounds__(256, 3)
void conv3d_kernel(const float* __restrict__ in,
                   const float* __restrict__ wA,
                   const float* __restrict__ wB)
{
    __shared__ float  tile[2][BD][TY+2][TW+2];
    __shared__ float2 wsp[2][54];     // (w,w) broadcast pairs

    const int tid = threadIdx.x;
    const int c   = blockIdx.z & 31;
    const int bb  = blockIdx.z >> 5;
    const int y0  = blockIdx.y * TY;
    const int x0  = blockIdx.x * TW;

    if (tid < 54) {
        float a = wA[c*54 + tid];
        wsp[0][tid] = make_float2(a, a);
        if (NC == 2) {
            float b = wB[c*54 + tid];
            wsp[1][tid] = make_float2(b, b);
        }
    }

    // ---- halo tile load: fully unrolled, immediate offsets, no div/mod ----
    {
        const int lx = tid & 63;       // 0..63
        const int wg = tid >> 6;       // 0..3: rows wg*5 .. wg*5+4
        const int gx  = x0 - 1 + lx;
        const bool okx  = (unsigned)gx  < (unsigned)W;
        const bool halo = (lx < 2);
        const int gx2 = gx + 64;
        const bool okx2 = halo && ((unsigned)gx2 < (unsigned)W);
        const int yyb = wg * 5;
        const int gyb = y0 - 1 + yyb;

        bool rok[5], rld[5], rld2[5];
        #pragma unroll
        for (int t = 0; t < 5; ++t) {
            const bool intile = (yyb + t) < (TY + 2);
            const bool iny    = (unsigned)(gyb + t) < (unsigned)H;
            rok[t]  = intile;
            rld[t]  = intile && iny && okx;
            rld2[t] = intile && iny && okx2;
        }

        const float* inb = in + ((size_t)(bb*CIN + 2*c))*CH_STRIDE;
        const float* p0  = inb + (ptrdiff_t)gyb * W + gx;

        #pragma unroll
        for (int din = 0; din < 2; ++din) {
            #pragma unroll
            for (int Bi = 0; Bi < BD; ++Bi) {
                const float* src = p0 + (din*BD + Bi)*HW;
                float* dst = &tile[din][Bi][0][0] + yyb*(TW+2) + lx;
                #pragma unroll
                for (int t = 0; t < 5; ++t) {
                    float v = rld[t] ? src[t*W] : 0.f;
                    if (rok[t]) dst[t*(TW+2)] = v;
                }
                if (halo) {
                    #pragma unroll
                    for (int t = 0; t < 5; ++t) {
                        float v2 = rld2[t] ? src[t*W + 64] : 0.f;
                        if (rok[t]) dst[t*(TW+2) + 64] = v2;
                    }
                }
            }
        }
    }
    __syncthreads();

    const int ty  = tid >> 4;
    const int tx4 = (tid & 15) << 2;

    unsigned long long acc[NC][BD][2];
    #pragma unroll
    for (int n = 0; n < NC; ++n)
        #pragma unroll
        for (int bo = 0; bo < BD; ++bo) { acc[n][bo][0] = 0ull; acc[n][bo][1] = 0ull; }

    #pragma unroll
    for (int din = 0; din < 2; ++din) {
        #pragma unroll
        for (int dy = 0; dy < 3; ++dy) {
            unsigned long long wr2[NC][9];
            #pragma unroll
            for (int n = 0; n < NC; ++n)
                #pragma unroll
                for (int dB = 0; dB < 3; ++dB)
                    #pragma unroll
                    for (int dx = 0; dx < 3; ++dx)
                        wr2[n][dB*3+dx] =
                            *(const unsigned long long*)&wsp[n][din*27 + dB*9 + dy*3 + dx];

            #pragma unroll
            for (int Bi = 0; Bi < BD; ++Bi) {
                const float* rp = &tile[din][Bi][ty + dy][tx4];
                unsigned long long P[5];
                P[0] = *(const unsigned long long*)(rp);        // (x0,x1)
                P[2] = *(const unsigned long long*)(rp + 2);    // (x2,x3)
                P[4] = *(const unsigned long long*)(rp + 4);    // (x4,x5)
                P[1] = pk(hi32(P[0]), lo32(P[2]));              // (x1,x2)
                P[3] = pk(hi32(P[2]), lo32(P[4]));              // (x3,x4)
                #pragma unroll
                for (int dB = 0; dB < 3; ++dB) {
                    const int Bo = Bi + 1 - dB;
                    if (Bo < 0 || Bo >= BD) continue;
                    #pragma unroll
                    for (int dx = 0; dx < 3; ++dx) {
                        #pragma unroll
                        for (int n = 0; n < NC; ++n) {
                            fma2(acc[n][Bo][0], P[dx],     wr2[n][dB*3+dx]);
                            fma2(acc[n][Bo][1], P[dx + 2], wr2[n][dB*3+dx]);
                        }
                    }
                }
            }
        }
    }

    const size_t ob = ((size_t)(bb*CATT + c))*CH_STRIDE
                    + (size_t)(y0 + ty)*W + x0 + tx4;
    #pragma unroll
    for (int Bo = 0; Bo < BD; ++Bo) {
        float2 a0 = u2f(acc[0][Bo][0]);
        float2 a1 = u2f(acc[0][Bo][1]);
        float4 r0 = make_float4(a0.x, a0.y, a1.x, a1.y);
        if (NC == 1) {
            *(float4*)(g_q + ob + (size_t)Bo*HW) = r0;
        } else {
            *(float4*)(g_k + ob + (size_t)Bo*HW) = r0;
            float2 b0 = u2f(acc[1][Bo][0]);
            float2 b1 = u2f(acc[1][Bo][1]);
            *(float4*)(g_v + ob + (size_t)Bo*HW) = make_float4(b0.x, b0.y, b1.x, b1.y);
        }
    }
}

// ============================================================================
// Attention (over B=5, 8 heads, head_dim=4) + grouped 1x1x1 projection.
// One thread per (b, y, x) point; loops heads; coalesced along x.
// ============================================================================
__global__ __launch_bounds__(256)
void attn_proj_kernel(const float* __restrict__ wproj, float* __restrict__ out)
{
    __shared__ float wp[64];
    if (threadIdx.x < 64) wp[threadIdx.x] = wproj[threadIdx.x];
    __syncthreads();

    const int p = blockIdx.x * 256 + threadIdx.x;
    if (p >= B_N * HW) return;
    const int bb = p >> 14;
    const int yx = p & (HW - 1);
    const size_t base = (size_t)bb * CATT * CH_STRIDE + yx;

    const float SCALE = 0.35355339059327373f;   // 8^{-1/2}

    #pragma unroll 1
    for (int hd = 0; hd < 8; ++hd) {
        float q[BD][4], k[BD][4], v[BD][4];
        #pragma unroll
        for (int d = 0; d < 4; ++d) {
            const size_t cb = base + (size_t)(hd*4 + d) * CH_STRIDE;
            #pragma unroll
            for (int Bi = 0; Bi < BD; ++Bi) {
                q[Bi][d] = g_q[cb + Bi*HW] * SCALE;
                k[Bi][d] = g_k[cb + Bi*HW];
                v[Bi][d] = g_v[cb + Bi*HW];
            }
        }
        #pragma unroll
        for (int i = 0; i < BD; ++i) {
            float s[BD];
            #pragma unroll
            for (int j = 0; j < BD; ++j) {
                float t = q[i][0] * k[j][0];
                t = fmaf(q[i][1], k[j][1], t);
                t = fmaf(q[i][2], k[j][2], t);
                t = fmaf(q[i][3], k[j][3], t);
                s[j] = t;
            }
            float m = s[0];
            #pragma unroll
            for (int j = 1; j < BD; ++j) m = fmaxf(m, s[j]);
            float e[BD], sum = 0.f;
            #pragma unroll
            for (int j = 0; j < BD; ++j) { e[j] = __expf(s[j] - m); sum += e[j]; }
            const float inv = 1.0f / sum;
            #pragma unroll
            for (int d = 0; d < 4; ++d) {
                float t = e[0] * v[0][d];
                #pragma unroll
                for (int j = 1; j < BD; ++j) t = fmaf(e[j], v[j][d], t);
                const float od = t * inv;
                const int ch = hd*4 + d;
                const size_t obx = ((size_t)(bb*CIN + 2*ch)*BD + i)*HW + yx;
                out[obx]           = od * wp[2*ch];
                out[obx + (size_t)BD*HW] = od * wp[2*ch + 1];
            }
        }
    }
}

extern "C" void kernel_launch(void* const* d_in, const int* in_sizes, int n_in,
                              void* d_out, int out_size) {
    const float* x     = (const float*)d_in[0];
    const float* last  = (const float*)d_in[1];
    const float* wq    = (const float*)d_in[2];
    const float* wk    = (const float*)d_in[3];
    const float* wv    = (const float*)d_in[4];
    const float* wproj = (const float*)d_in[5];
    float* out = (float*)d_out;

    dim3 cgrid(W/TW, H/TY, B_N*CATT);   // (2, 8, 256)
    conv3d_kernel<1><<<cgrid, 256>>>(x,    wq, nullptr);
    conv3d_kernel<2><<<cgrid, 256>>>(last, wk, wv);
    attn_proj_kernel<<<(B_N*HW + 255)/256, 256>>>(wproj, out);
}